// round 1
// baseline (speedup 1.0000x reference)
#include <cuda_runtime.h>
#include <cuda_bf16.h>
#include <cstdint>

typedef unsigned long long u64;

#define M_SLOTS 60
#define CHANS   256
#define HW      3136           // 56*56
#define NTOT    802816         // 256*3136 elements per memory slot
#define BATCH   64
#define EPS     1e-8f

// Scratch (device globals — no allocation allowed)
__device__ float g_mem_avg[M_SLOTS * CHANS];     // [m][c]
__device__ float g_wT[M_SLOTS * BATCH];          // [m][b]  (transposed weights)

// ---------------- packed f32x2 helpers ----------------
__device__ __forceinline__ u64 fma2(u64 a, u64 b, u64 c) {
    u64 d;
    asm("fma.rn.f32x2 %0, %1, %2, %3;" : "=l"(d) : "l"(a), "l"(b), "l"(c));
    return d;
}
__device__ __forceinline__ u64 pack2(float lo, float hi) {
    u64 d;
    unsigned int l = __float_as_uint(lo), h = __float_as_uint(hi);
    asm("mov.b64 %0, {%1, %2};" : "=l"(d) : "r"(l), "r"(h));
    return d;
}
__device__ __forceinline__ void unpack2(u64 p, float& lo, float& hi) {
    unsigned int a, b;
    asm("mov.b64 {%0, %1}, %2;" : "=r"(a), "=r"(b) : "l"(p));
    lo = __uint_as_float(a);
    hi = __uint_as_float(b);
}

// ---------------- kernel 1: mean over H,W ----------------
// One block per (m,c) row: 3136 floats = 784 float4, 256 threads.
__global__ void mean_kernel(const float* __restrict__ mem) {
    const int r = blockIdx.x;  // 0 .. 60*256-1
    const float4* p = (const float4*)(mem + (size_t)r * HW);
    float s = 0.0f;
    for (int i = threadIdx.x; i < HW / 4; i += 256) {
        float4 v = __ldg(p + i);
        s += (v.x + v.y) + (v.z + v.w);
    }
    __shared__ float red[256];
    red[threadIdx.x] = s;
    __syncthreads();
    for (int o = 128; o > 0; o >>= 1) {
        if (threadIdx.x < o) red[threadIdx.x] += red[threadIdx.x + o];
        __syncthreads();
    }
    if (threadIdx.x == 0) g_mem_avg[r] = red[0] * (1.0f / (float)HW);
}

// ---------------- kernel 2: cosine sim + softmax -> weights ----------------
// One block per batch b, 256 threads (8 warps).
__global__ void weights_kernel(const float* __restrict__ q) {
    const int b = blockIdx.x;
    const int tid = threadIdx.x;
    const int lane = tid & 31;
    const int wrp = tid >> 5;

    __shared__ float s_cos[M_SLOTS];
    __shared__ float s_qn;

    // q norm (warp 0)
    if (wrp == 0) {
        float s = 0.0f;
        const float* qr = q + b * CHANS;
        for (int i = lane; i < CHANS; i += 32) { float v = qr[i]; s += v * v; }
        for (int o = 16; o > 0; o >>= 1) s += __shfl_xor_sync(0xffffffffu, s, o);
        if (lane == 0) s_qn = sqrtf(s);
    }
    __syncthreads();
    const float qn = fmaxf(s_qn, EPS);

    // dots + mem norms: warp w handles m = w, w+8, ...
    for (int m = wrp; m < M_SLOTS; m += 8) {
        const float* mr = g_mem_avg + m * CHANS;
        const float* qr = q + b * CHANS;
        float dot = 0.0f, mn2 = 0.0f;
        for (int i = lane; i < CHANS; i += 32) {
            float mv = mr[i];
            dot = fmaf(mv, qr[i], dot);
            mn2 = fmaf(mv, mv, mn2);
        }
        for (int o = 16; o > 0; o >>= 1) {
            dot += __shfl_xor_sync(0xffffffffu, dot, o);
            mn2 += __shfl_xor_sync(0xffffffffu, mn2, o);
        }
        if (lane == 0) s_cos[m] = dot / (qn * fmaxf(sqrtf(mn2), EPS));
    }
    __syncthreads();

    // softmax over 60 slots (warp 0), write transposed weights
    if (wrp == 0) {
        float v0 = (lane < M_SLOTS) ? s_cos[lane] : -1e30f;
        float v1 = (lane + 32 < M_SLOTS) ? s_cos[lane + 32] : -1e30f;
        float mx = fmaxf(v0, v1);
        for (int o = 16; o > 0; o >>= 1) mx = fmaxf(mx, __shfl_xor_sync(0xffffffffu, mx, o));
        float e0 = (lane < M_SLOTS) ? expf(v0 - mx) : 0.0f;
        float e1 = (lane + 32 < M_SLOTS) ? expf(v1 - mx) : 0.0f;
        float sm = e0 + e1;
        for (int o = 16; o > 0; o >>= 1) sm += __shfl_xor_sync(0xffffffffu, sm, o);
        float inv = 1.0f / sm;
        if (lane < M_SLOTS)       g_wT[lane * BATCH + b]        = e0 * inv;
        if (lane + 32 < M_SLOTS)  g_wT[(lane + 32) * BATCH + b] = e1 * inv;
    }
}

// ---------------- kernel 3: einsum bm,mchw->bchw ----------------
// Thread: 4 spatial elems (float4) x 16 batches as 8 f32x2 batch-pairs.
// Grid (4 btiles fastest, 784 chunks) => 4 btiles of same chunk co-resident,
// memory_pool DRAM-read ~once, re-reads served from L2.
__global__ __launch_bounds__(256, 2) void einsum_kernel(const float* __restrict__ mem,
                                                        float* __restrict__ out) {
    __shared__ u64 s_wp[M_SLOTS][8];   // pre-packed (w[b], w[b+1]) for this btile
    const int btile = blockIdx.x;      // 0..3 -> batches [btile*16, btile*16+16)
    const int tid = threadIdx.x;

    for (int i = tid; i < M_SLOTS * 8; i += 256) {
        int m = i >> 3, bp = i & 7;
        const float* wsrc = g_wT + m * BATCH + btile * 16 + bp * 2;
        s_wp[m][bp] = pack2(wsrc[0], wsrc[1]);
    }
    __syncthreads();

    const size_t n0 = (size_t)blockIdx.y * 1024 + (size_t)tid * 4;

    u64 acc[8][4];
#pragma unroll
    for (int bp = 0; bp < 8; bp++)
#pragma unroll
        for (int v = 0; v < 4; v++) acc[bp][v] = 0ull;   // bit pattern 0 == (0.f, 0.f)

#pragma unroll 4
    for (int m = 0; m < M_SLOTS; m++) {
        float4 val = __ldg((const float4*)(mem + (size_t)m * NTOT + n0));
        u64 d0 = pack2(val.x, val.x);
        u64 d1 = pack2(val.y, val.y);
        u64 d2 = pack2(val.z, val.z);
        u64 d3 = pack2(val.w, val.w);
#pragma unroll
        for (int bp = 0; bp < 8; bp++) {
            u64 wp = s_wp[m][bp];
            acc[bp][0] = fma2(d0, wp, acc[bp][0]);
            acc[bp][1] = fma2(d1, wp, acc[bp][1]);
            acc[bp][2] = fma2(d2, wp, acc[bp][2]);
            acc[bp][3] = fma2(d3, wp, acc[bp][3]);
        }
    }

#pragma unroll
    for (int bp = 0; bp < 8; bp++) {
        float lo[4], hi[4];
#pragma unroll
        for (int v = 0; v < 4; v++) unpack2(acc[bp][v], lo[v], hi[v]);
        const int b0 = btile * 16 + bp * 2;
        *(float4*)(out + (size_t)b0 * NTOT + n0)       = make_float4(lo[0], lo[1], lo[2], lo[3]);
        *(float4*)(out + (size_t)(b0 + 1) * NTOT + n0) = make_float4(hi[0], hi[1], hi[2], hi[3]);
    }
}

// ---------------- launcher ----------------
extern "C" void kernel_launch(void* const* d_in, const int* in_sizes, int n_in,
                              void* d_out, int out_size) {
    const float* mem = (const float*)d_in[0];
    const float* q   = (const float*)d_in[1];
    // Safety: memory_pool is the big input (48,168,960 elems), query is 16,384.
    if (n_in >= 2 && in_sizes[0] < in_sizes[1]) {
        const float* t = mem; mem = q; q = t;
    }
    float* out = (float*)d_out;

    mean_kernel<<<M_SLOTS * CHANS, 256>>>(mem);
    weights_kernel<<<BATCH, 256>>>(q);
    einsum_kernel<<<dim3(4, NTOT / 1024), 256>>>(mem, out);
}